// round 8
// baseline (speedup 1.0000x reference)
#include <cuda_runtime.h>
#include <cuda_fp16.h>
#include <cstdint>

// Problem: x [8,4096,512] f32, codebook [4096,512] f32
//   N = 32768 tokens, M = 4096 codes, K = 512
// Out (f32, concatenated): q_st [N*512], commitment_loss [N], cb_n [M*512]
//
// argmax_m cos(x, cb_m) via fp16 3-block limb GEMM on mma.sync (HMMA):
//   A' = [Hx | Mx*32 | Hx/32]  (K'=1536)
//   B' = [Hc | Hc/32 | Mc*32]  (raw codebook)
//   A'.B' = (x - rx).(c - rc) + ~1e-8 ; epilogue scales col by 1/||cb_m||.
// R8: CTA 128x128 with 4 warps of 64x64 (128 thr), 3-stage 96KB pipeline
//     -> keeps 2 CTAs/SM (R7 lesson) while halving LDSM bytes/MAC.

#define NTOK   32768
#define MCODE  4096
#define KDIM   512
#define KSPLIT 1536
#define EPSN   1e-12f

#define TILEM 128                            // tokens per CTA
#define TILEN 128                            // codes per CTA
#define KC    64                             // fp16 per k-chunk (128 B rows)
#define NSTAGE 3
#define ATILE_BYTES (TILEM * 128)            // 16384
#define BTILE_BYTES (TILEN * 128)            // 16384
#define STAGE_BYTES (ATILE_BYTES + BTILE_BYTES)
#define DYN_SMEM    (NSTAGE * STAGE_BYTES)   // 98304 -> 2 CTAs/SM
#define NITER       (KSPLIT / KC)            // 24

// ---------------- device scratch (no allocs allowed) ----------------
__device__ __half             g_xs[(size_t)NTOK * KSPLIT];
__device__ __half             g_bs[(size_t)MCODE * KSPLIT];
__device__ float              g_cbn[(size_t)MCODE * KDIM];   // normalized cb
__device__ float              g_invnb[MCODE];                // 1/max(||cb||,eps)
__device__ float              g_invnx[NTOK];
__device__ unsigned long long g_best[NTOK];

// ---------------- helpers ----------------
__device__ __forceinline__ uint32_t smem_u32(const void* p) {
    uint32_t a;
    asm("{ .reg .u64 t; cvta.to.shared.u64 t, %1; cvt.u32.u64 %0, t; }"
        : "=r"(a) : "l"(p));
    return a;
}
__device__ __forceinline__ void cp_async16(uint32_t s, const void* g) {
    asm volatile("cp.async.cg.shared.global [%0], [%1], 16;" :: "r"(s), "l"(g));
}
__device__ __forceinline__ void ldsm_x4(uint32_t* r, uint32_t addr) {
    asm volatile("ldmatrix.sync.aligned.m8n8.x4.shared.b16 {%0,%1,%2,%3}, [%4];"
                 : "=r"(r[0]), "=r"(r[1]), "=r"(r[2]), "=r"(r[3]) : "r"(addr));
}
__device__ __forceinline__ void mma16816(float* c, const uint32_t* a,
                                         const uint32_t* b) {
    asm volatile(
        "mma.sync.aligned.m16n8k16.row.col.f32.f16.f16.f32 "
        "{%0,%1,%2,%3}, {%4,%5,%6,%7}, {%8,%9}, {%0,%1,%2,%3};"
        : "+f"(c[0]), "+f"(c[1]), "+f"(c[2]), "+f"(c[3])
        : "r"(a[0]), "r"(a[1]), "r"(a[2]), "r"(a[3]), "r"(b[0]), "r"(b[1]));
}

// monotone float<->uint (order-preserving); key = (flipped dot || ~idx)
__device__ __forceinline__ unsigned flip_f(unsigned fb) {
    return (fb & 0x80000000u) ? ~fb : (fb | 0x80000000u);
}
__device__ __forceinline__ unsigned unflip_f(unsigned u) {
    return (u & 0x80000000u) ? (u & 0x7FFFFFFFu) : ~u;
}
__device__ __forceinline__ unsigned long long make_key(unsigned fbits, int idx) {
    return (((unsigned long long)flip_f(fbits)) << 32) |
           (unsigned long long)(0xFFFFFFFFu - (unsigned)idx);
}

// ---------------- kernel 1: codebook norms + normalized copy + limbs ----------------
__global__ void norm_cb_kernel(const float* __restrict__ cb,
                               float* __restrict__ out_cb) {
    int row = blockIdx.x;
    int tid = threadIdx.x;   // 128 threads x 4 floats
    const float4 v = *(const float4*)(cb + (size_t)row * KDIM + tid * 4);
    float s = v.x * v.x + v.y * v.y + v.z * v.z + v.w * v.w;
    #pragma unroll
    for (int off = 16; off > 0; off >>= 1) s += __shfl_down_sync(~0u, s, off);
    __shared__ float ws[4]; __shared__ float sinv;
    if ((tid & 31) == 0) ws[tid >> 5] = s;
    __syncthreads();
    if (tid == 0) {
        float inv = 1.0f / fmaxf(sqrtf(ws[0] + ws[1] + ws[2] + ws[3]), EPSN);
        sinv = inv;
        g_invnb[row] = inv;
    }
    __syncthreads();
    float inv = sinv;
    float o[4] = {v.x * inv, v.y * inv, v.z * inv, v.w * inv};
    size_t fb = (size_t)row * KDIM + tid * 4;
    *(float4*)(g_cbn + fb) = *(float4*)o;
    if (out_cb) *(float4*)(out_cb + fb) = *(float4*)o;
    // raw-cb limbs: [Hc | Hc/32 | Mc*32]
    float f[4] = {v.x, v.y, v.z, v.w};
    __half* base = g_bs + (size_t)row * KSPLIT + tid * 4;
    #pragma unroll
    for (int j = 0; j < 4; j++) {
        __half h = __float2half_rn(f[j]);
        float hf = __half2float(h);
        base[j]        = h;
        base[512 + j]  = __float2half_rn(hf * 0.03125f);
        base[1024 + j] = __float2half_rn((f[j] - hf) * 32.0f);
    }
}

// ---------------- kernel 2: x inv-norms + limbs + init best ----------------
__global__ void norm_x_kernel(const float* __restrict__ x) {
    int row = blockIdx.x;
    int tid = threadIdx.x;
    const float4 v = *(const float4*)(x + (size_t)row * KDIM + tid * 4);
    float s = v.x * v.x + v.y * v.y + v.z * v.z + v.w * v.w;
    #pragma unroll
    for (int off = 16; off > 0; off >>= 1) s += __shfl_down_sync(~0u, s, off);
    __shared__ float ws[4];
    if ((tid & 31) == 0) ws[tid >> 5] = s;
    __syncthreads();
    if (tid == 0) {
        g_invnx[row] = 1.0f / fmaxf(sqrtf(ws[0] + ws[1] + ws[2] + ws[3]), EPSN);
        g_best[row] = 0ull;
    }
    // x limbs: [Hx | Mx*32 | Hx/32]
    float f[4] = {v.x, v.y, v.z, v.w};
    __half* base = g_xs + (size_t)row * KSPLIT + tid * 4;
    #pragma unroll
    for (int j = 0; j < 4; j++) {
        __half h = __float2half_rn(f[j]);
        float hf = __half2float(h);
        base[j]        = h;
        base[512 + j]  = __float2half_rn((f[j] - hf) * 32.0f);
        base[1024 + j] = __float2half_rn(hf * 0.03125f);
    }
}

// ---------------- kernel 3: HMMA GEMM (K'=1536) + cosine rescale + argmax ----------------
// grid (MCODE/TILEN=32 inner, NTOK/TILEM=256); 128 threads; 4 warps of 64x64.
extern "C" __global__ void __launch_bounds__(128, 2)
vq_hmma_kernel(unsigned long long* __restrict__ best) {
    extern __shared__ char smem[];
    __shared__ unsigned long long s_best[TILEM];
    __shared__ float s_invb[TILEN];

    const int tid = threadIdx.x;
    const int wid = tid >> 5;
    const int lid = tid & 31;
    const int mBase = blockIdx.x * TILEN;   // codes
    const int nBase = blockIdx.y * TILEM;   // tokens

    s_best[tid] = 0ull;
    s_invb[tid] = g_invnb[mBase + tid];

    const uint32_t sbase = smem_u32(smem);

    // ---- cp.async coords: each thread owns one full 128B row of A and of B ----
    const __half* aSrc = g_xs + (size_t)(nBase + tid) * KSPLIT;
    const __half* bSrc = g_bs + (size_t)(mBase + tid) * KSPLIT;
    uint32_t aDst[8], bDst[8];
    {
        const uint32_t xr = (tid & 7) << 4;   // SW128 xor
        #pragma unroll
        for (int q = 0; q < 8; q++) {
            uint32_t off = tid * 128 + ((q * 16) ^ xr);
            aDst[q] = off;
            bDst[q] = ATILE_BYTES + off;
        }
    }

    // ---- ldmatrix lane addressing (4 warps in 2x2, warp tile 64x64) ----
    const int wRow = (wid & 1) * 64;    // token rows of this warp
    const int wCol = (wid >> 1) * 64;   // code cols of this warp
    uint32_t aRowOff[4], aXor[4];
    #pragma unroll
    for (int mt = 0; mt < 4; mt++) {
        int r = wRow + mt * 16 + (lid & 7) + ((lid >> 3) & 1) * 8;
        aRowOff[mt] = r * 128;
        aXor[mt] = (r & 7) << 4;
    }
    const uint32_t aCb = ((lid >> 4) & 1) * 16;
    uint32_t bRowOff[4], bXor[4];
    #pragma unroll
    for (int np = 0; np < 4; np++) {
        int r = wCol + np * 16 + (lid & 7) + ((lid >> 4) & 1) * 8;
        bRowOff[np] = ATILE_BYTES + r * 128;
        bXor[np] = (r & 7) << 4;
    }
    const uint32_t bCb = ((lid >> 3) & 1) * 16;

    float acc[4][8][4];
    #pragma unroll
    for (int mt = 0; mt < 4; mt++)
        #pragma unroll
        for (int nt = 0; nt < 8; nt++)
            #pragma unroll
            for (int j = 0; j < 4; j++) acc[mt][nt][j] = 0.0f;

#define ISSUE(stage, bufi) do {                                           \
        uint32_t sb_ = sbase + (bufi) * STAGE_BYTES;                      \
        const __half* a_ = aSrc + (stage) * KC;                           \
        const __half* b_ = bSrc + (stage) * KC;                           \
        _Pragma("unroll")                                                 \
        for (int q = 0; q < 8; q++) cp_async16(sb_ + aDst[q], a_ + q * 8);\
        _Pragma("unroll")                                                 \
        for (int q = 0; q < 8; q++) cp_async16(sb_ + bDst[q], b_ + q * 8);\
    } while (0)

    // prologue: stages 0..2
    #pragma unroll
    for (int s = 0; s < NSTAGE; s++) {
        ISSUE(s, s);
        asm volatile("cp.async.commit_group;" ::: "memory");
    }

    int buf = 0;
    for (int i = 0; i < NITER; i++) {
        asm volatile("cp.async.wait_group 2;" ::: "memory");
        __syncthreads();

        const uint32_t sb = sbase + buf * STAGE_BYTES;
        #pragma unroll
        for (int ks = 0; ks < 4; ks++) {
            uint32_t a[4][4];
            #pragma unroll
            for (int mt = 0; mt < 4; mt++)
                ldsm_x4(a[mt], sb + aRowOff[mt] + (((uint32_t)ks * 32 + aCb) ^ aXor[mt]));
            uint32_t b[4][4];
            #pragma unroll
            for (int np = 0; np < 4; np++)
                ldsm_x4(b[np], sb + bRowOff[np] + (((uint32_t)ks * 32 + bCb) ^ bXor[np]));
            #pragma unroll
            for (int mt = 0; mt < 4; mt++)
                #pragma unroll
                for (int nt = 0; nt < 8; nt++)
                    mma16816(acc[mt][nt], a[mt], &b[nt >> 1][(nt & 1) * 2]);
        }
        __syncthreads();

        if (i + NSTAGE < NITER) ISSUE(i + NSTAGE, buf);
        asm volatile("cp.async.commit_group;" ::: "memory");
        buf = (buf == NSTAGE - 1) ? 0 : buf + 1;
    }

    // ---- cosine rescale + fused argmax ----
    #pragma unroll
    for (int mt = 0; mt < 4; mt++) {
        #pragma unroll
        for (int sub = 0; sub < 2; sub++) {
            unsigned long long bk = 0ull;
            #pragma unroll
            for (int nt = 0; nt < 8; nt++) {
                #pragma unroll
                for (int j = 0; j < 2; j++) {
                    int cl = wCol + nt * 8 + 2 * (lid & 3) + j;
                    float f = acc[mt][nt][sub * 2 + j] * s_invb[cl];
                    unsigned long long k = make_key(__float_as_uint(f), mBase + cl);
                    if (k > bk) bk = k;
                }
            }
            unsigned long long o;
            o = __shfl_xor_sync(~0u, bk, 1); if (o > bk) bk = o;
            o = __shfl_xor_sync(~0u, bk, 2); if (o > bk) bk = o;
            if ((lid & 3) == 0) {
                int rowLocal = wRow + mt * 16 + sub * 8 + (lid >> 2);
                atomicMax(&s_best[rowLocal], bk);
            }
        }
    }
    __syncthreads();
    atomicMax(&best[nBase + tid], s_best[tid]);
}

// ---------------- kernel 4: finalize (gather q_st + loss) ----------------
__global__ void finalize_kernel(float* __restrict__ q_out,
                                float* __restrict__ loss_out) {
    int n = blockIdx.x;
    int tid = threadIdx.x;   // 128 threads, one float4 each
    unsigned long long pk = g_best[n];
    unsigned idx = 0xFFFFFFFFu - (unsigned)(pk & 0xFFFFFFFFull);
    float dot = __uint_as_float(unflip_f((unsigned)(pk >> 32)));  // = x.cb_norm
    float4 v = *(const float4*)(g_cbn + (size_t)idx * KDIM + tid * 4);
    *(float4*)(q_out + (size_t)n * KDIM + tid * 4) = v;
    if (tid == 0 && loss_out)
        loss_out[n] = 1.0f - dot * g_invnx[n];
}

// ---------------- host launch ----------------
extern "C" void kernel_launch(void* const* d_in, const int* in_sizes, int n_in,
                              void* d_out, int out_size) {
    const float* x  = (const float*)d_in[0];
    const float* cb = (const float*)d_in[1];
    const int N = in_sizes[0] / KDIM;   // 32768
    const int M = in_sizes[1] / KDIM;   // 4096

    float* out = (float*)d_out;
    float* q_out = out;
    float* loss_out = nullptr;
    float* cb_out = nullptr;
    long long need_full = (long long)N * KDIM + N + (long long)M * KDIM;
    if ((long long)out_size >= need_full) {
        loss_out = out + (size_t)N * KDIM;
        cb_out = loss_out + N;
    } else if ((long long)out_size >= (long long)N * KDIM + N) {
        loss_out = out + (size_t)N * KDIM;
    }

    cudaFuncSetAttribute(vq_hmma_kernel,
                         cudaFuncAttributeMaxDynamicSharedMemorySize, DYN_SMEM);

    // device-symbol addresses MUST come from cudaGetSymbolAddress (R1 lesson)
    unsigned long long* bestp = nullptr;
    cudaGetSymbolAddress((void**)&bestp, g_best);

    norm_cb_kernel<<<M, 128>>>(cb, cb_out);
    norm_x_kernel<<<N, 128>>>(x);

    dim3 grid(M / TILEN, N / TILEM);   // codes inner -> B' (12 MB) hot in L2
    vq_hmma_kernel<<<grid, 128, DYN_SMEM>>>(bestp);

    finalize_kernel<<<N, 128>>>(q_out, loss_out);
}

// round 9
// speedup vs baseline: 1.5219x; 1.5219x over previous
#include <cuda_runtime.h>
#include <cuda_fp16.h>
#include <cstdint>

// Problem: x [8,4096,512] f32, codebook [4096,512] f32
//   N = 32768 tokens, M = 4096 codes, K = 512
// Out (f32, concatenated): q_st [N*512], commitment_loss [N], cb_n [M*512]
//
// argmax_m cos(x, cb_m) via fp16 3-block limb GEMM on mma.sync (HMMA):
//   A' = [Hx | Mx*32 | Hx/32]  (K'=1536)
//   B' = [Hc | Hc/32 | Mc*32]  (raw codebook)
//   A'.B' = (x - rx).(c - rc) + ~1e-8 ; epilogue scales col by 1/||cb_m||.
// R9 = R6 config (CTA 128x128, 8 warps of 32x64, 2 CTAs/SM) with a
//      single-__syncthreads 3-stage pipeline (issue-before-compute).

#define NTOK   32768
#define MCODE  4096
#define KDIM   512
#define KSPLIT 1536
#define EPSN   1e-12f

#define TILE        128
#define KC          64                      // fp16 per k-chunk (128 B rows)
#define NSTAGE      3
#define ATILE_BYTES (TILE * 128)            // 16384
#define STAGE_BYTES (2 * ATILE_BYTES)       // A + B
#define DYN_SMEM    (NSTAGE * STAGE_BYTES)  // 98304 -> 2 CTAs/SM
#define NITER       (KSPLIT / KC)           // 24

// ---------------- device scratch (no allocs allowed) ----------------
__device__ __half             g_xs[(size_t)NTOK * KSPLIT];
__device__ __half             g_bs[(size_t)MCODE * KSPLIT];
__device__ float              g_cbn[(size_t)MCODE * KDIM];   // normalized cb
__device__ float              g_invnb[MCODE];                // 1/max(||cb||,eps)
__device__ float              g_invnx[NTOK];
__device__ unsigned long long g_best[NTOK];

// ---------------- helpers ----------------
__device__ __forceinline__ uint32_t smem_u32(const void* p) {
    uint32_t a;
    asm("{ .reg .u64 t; cvta.to.shared.u64 t, %1; cvt.u32.u64 %0, t; }"
        : "=r"(a) : "l"(p));
    return a;
}
__device__ __forceinline__ void cp_async16(uint32_t s, const void* g) {
    asm volatile("cp.async.cg.shared.global [%0], [%1], 16;" :: "r"(s), "l"(g));
}
__device__ __forceinline__ void ldsm_x4(uint32_t* r, uint32_t addr) {
    asm volatile("ldmatrix.sync.aligned.m8n8.x4.shared.b16 {%0,%1,%2,%3}, [%4];"
                 : "=r"(r[0]), "=r"(r[1]), "=r"(r[2]), "=r"(r[3]) : "r"(addr));
}
__device__ __forceinline__ void mma16816(float* c, const uint32_t* a,
                                         const uint32_t* b) {
    asm volatile(
        "mma.sync.aligned.m16n8k16.row.col.f32.f16.f16.f32 "
        "{%0,%1,%2,%3}, {%4,%5,%6,%7}, {%8,%9}, {%0,%1,%2,%3};"
        : "+f"(c[0]), "+f"(c[1]), "+f"(c[2]), "+f"(c[3])
        : "r"(a[0]), "r"(a[1]), "r"(a[2]), "r"(a[3]), "r"(b[0]), "r"(b[1]));
}

// monotone float<->uint (order-preserving); key = (flipped dot || ~idx)
__device__ __forceinline__ unsigned flip_f(unsigned fb) {
    return (fb & 0x80000000u) ? ~fb : (fb | 0x80000000u);
}
__device__ __forceinline__ unsigned unflip_f(unsigned u) {
    return (u & 0x80000000u) ? (u & 0x7FFFFFFFu) : ~u;
}
__device__ __forceinline__ unsigned long long make_key(unsigned fbits, int idx) {
    return (((unsigned long long)flip_f(fbits)) << 32) |
           (unsigned long long)(0xFFFFFFFFu - (unsigned)idx);
}

// ---------------- kernel 1: codebook norms + normalized copy + limbs ----------------
__global__ void norm_cb_kernel(const float* __restrict__ cb,
                               float* __restrict__ out_cb) {
    int row = blockIdx.x;
    int tid = threadIdx.x;   // 128 threads x 4 floats
    const float4 v = *(const float4*)(cb + (size_t)row * KDIM + tid * 4);
    float s = v.x * v.x + v.y * v.y + v.z * v.z + v.w * v.w;
    #pragma unroll
    for (int off = 16; off > 0; off >>= 1) s += __shfl_down_sync(~0u, s, off);
    __shared__ float ws[4]; __shared__ float sinv;
    if ((tid & 31) == 0) ws[tid >> 5] = s;
    __syncthreads();
    if (tid == 0) {
        float inv = 1.0f / fmaxf(sqrtf(ws[0] + ws[1] + ws[2] + ws[3]), EPSN);
        sinv = inv;
        g_invnb[row] = inv;
    }
    __syncthreads();
    float inv = sinv;
    float o[4] = {v.x * inv, v.y * inv, v.z * inv, v.w * inv};
    size_t fb = (size_t)row * KDIM + tid * 4;
    *(float4*)(g_cbn + fb) = *(float4*)o;
    if (out_cb) *(float4*)(out_cb + fb) = *(float4*)o;
    // raw-cb limbs: [Hc | Hc/32 | Mc*32]
    float f[4] = {v.x, v.y, v.z, v.w};
    __half* base = g_bs + (size_t)row * KSPLIT + tid * 4;
    #pragma unroll
    for (int j = 0; j < 4; j++) {
        __half h = __float2half_rn(f[j]);
        float hf = __half2float(h);
        base[j]        = h;
        base[512 + j]  = __float2half_rn(hf * 0.03125f);
        base[1024 + j] = __float2half_rn((f[j] - hf) * 32.0f);
    }
}

// ---------------- kernel 2: x inv-norms + limbs + init best ----------------
__global__ void norm_x_kernel(const float* __restrict__ x) {
    int row = blockIdx.x;
    int tid = threadIdx.x;
    const float4 v = *(const float4*)(x + (size_t)row * KDIM + tid * 4);
    float s = v.x * v.x + v.y * v.y + v.z * v.z + v.w * v.w;
    #pragma unroll
    for (int off = 16; off > 0; off >>= 1) s += __shfl_down_sync(~0u, s, off);
    __shared__ float ws[4];
    if ((tid & 31) == 0) ws[tid >> 5] = s;
    __syncthreads();
    if (tid == 0) {
        g_invnx[row] = 1.0f / fmaxf(sqrtf(ws[0] + ws[1] + ws[2] + ws[3]), EPSN);
        g_best[row] = 0ull;
    }
    // x limbs: [Hx | Mx*32 | Hx/32]
    float f[4] = {v.x, v.y, v.z, v.w};
    __half* base = g_xs + (size_t)row * KSPLIT + tid * 4;
    #pragma unroll
    for (int j = 0; j < 4; j++) {
        __half h = __float2half_rn(f[j]);
        float hf = __half2float(h);
        base[j]        = h;
        base[512 + j]  = __float2half_rn((f[j] - hf) * 32.0f);
        base[1024 + j] = __float2half_rn(hf * 0.03125f);
    }
}

// ---------------- kernel 3: HMMA GEMM (K'=1536) + cosine rescale + argmax ----------------
// grid (MCODE/TILE=32 inner, NTOK/TILE=256); 256 threads; warp tile 32x64.
extern "C" __global__ void __launch_bounds__(256, 2)
vq_hmma_kernel(unsigned long long* __restrict__ best) {
    extern __shared__ char smem[];
    __shared__ unsigned long long s_best[TILE];
    __shared__ float s_invb[TILE];

    const int tid = threadIdx.x;
    const int wid = tid >> 5;
    const int lid = tid & 31;
    const int mBase = blockIdx.x * TILE;   // codes
    const int nBase = blockIdx.y * TILE;   // tokens

    if (tid < TILE) {
        s_best[tid] = 0ull;
        s_invb[tid] = g_invnb[mBase + tid];
    }

    const uint32_t sbase = smem_u32(smem);

    // ---- cp.async coordinates: thread -> (row, 64B-half), 4x16B each op ----
    const int ldrow = tid >> 1;
    const int ldhalf = tid & 1;
    const __half* aSrc = g_xs + (size_t)(nBase + ldrow) * KSPLIT + ldhalf * 32;
    const __half* bSrc = g_bs + (size_t)(mBase + ldrow) * KSPLIT + ldhalf * 32;
    uint32_t aDst[4], bDst[4];
    {
        const uint32_t xr = (ldrow & 7) << 4;   // SW128 xor
        #pragma unroll
        for (int q = 0; q < 4; q++) {
            uint32_t cbyte = ldhalf * 64 + q * 16;
            uint32_t off = ldrow * 128 + (cbyte ^ xr);
            aDst[q] = off;
            bDst[q] = ATILE_BYTES + off;
        }
    }

    // ---- ldmatrix lane addressing ----
    const int wRow = (wid & 3) * 32;   // token rows of this warp
    const int wCol = (wid >> 2) * 64;  // code cols of this warp
    uint32_t aRowOff[2], aXor[2];
    #pragma unroll
    for (int mt = 0; mt < 2; mt++) {
        int r = wRow + mt * 16 + (lid & 7) + ((lid >> 3) & 1) * 8;
        aRowOff[mt] = r * 128;
        aXor[mt] = (r & 7) << 4;
    }
    const uint32_t aCb = ((lid >> 4) & 1) * 16;
    uint32_t bRowOff[4], bXor[4];
    #pragma unroll
    for (int np = 0; np < 4; np++) {
        int r = wCol + np * 16 + (lid & 7) + ((lid >> 4) & 1) * 8;
        bRowOff[np] = ATILE_BYTES + r * 128;
        bXor[np] = (r & 7) << 4;
    }
    const uint32_t bCb = ((lid >> 3) & 1) * 16;

    float acc[2][8][4];
    #pragma unroll
    for (int mt = 0; mt < 2; mt++)
        #pragma unroll
        for (int nt = 0; nt < 8; nt++)
            #pragma unroll
            for (int j = 0; j < 4; j++) acc[mt][nt][j] = 0.0f;

#define ISSUE(stage, bufi) do {                                           \
        uint32_t sb_ = sbase + (bufi) * STAGE_BYTES;                      \
        const __half* a_ = aSrc + (stage) * KC;                           \
        const __half* b_ = bSrc + (stage) * KC;                           \
        _Pragma("unroll")                                                 \
        for (int q = 0; q < 4; q++) cp_async16(sb_ + aDst[q], a_ + q * 8);\
        _Pragma("unroll")                                                 \
        for (int q = 0; q < 4; q++) cp_async16(sb_ + bDst[q], b_ + q * 8);\
    } while (0)

    // prologue: stages 0,1 in flight (buffers 0,1; buffer 2 free)
    ISSUE(0, 0);
    asm volatile("cp.async.commit_group;" ::: "memory");
    ISSUE(1, 1);
    asm volatile("cp.async.commit_group;" ::: "memory");

    int buf = 0;                       // buffer holding stage i
    int ibuf = 2;                      // free buffer for stage i+2
    for (int i = 0; i < NITER; i++) {
        asm volatile("cp.async.wait_group 1;" ::: "memory");   // stage i ready
        __syncthreads();   // also: every warp done computing stage i-1 -> ibuf free

        // issue stage i+2 into the freed buffer BEFORE compute (overlap)
        if (i + 2 < NITER) ISSUE(i + 2, ibuf);
        asm volatile("cp.async.commit_group;" ::: "memory");

        const uint32_t sb = sbase + buf * STAGE_BYTES;
        #pragma unroll
        for (int ks = 0; ks < 4; ks++) {
            uint32_t a[2][4];
            #pragma unroll
            for (int mt = 0; mt < 2; mt++)
                ldsm_x4(a[mt], sb + aRowOff[mt] + (((uint32_t)ks * 32 + aCb) ^ aXor[mt]));
            uint32_t b[4][4];
            #pragma unroll
            for (int np = 0; np < 4; np++)
                ldsm_x4(b[np], sb + bRowOff[np] + (((uint32_t)ks * 32 + bCb) ^ bXor[np]));
            #pragma unroll
            for (int mt = 0; mt < 2; mt++)
                #pragma unroll
                for (int nt = 0; nt < 8; nt++)
                    mma16816(acc[mt][nt], a[mt], &b[nt >> 1][(nt & 1) * 2]);
        }

        buf = (buf == NSTAGE - 1) ? 0 : buf + 1;
        ibuf = (ibuf == NSTAGE - 1) ? 0 : ibuf + 1;
    }

    // ---- cosine rescale + fused argmax ----
    #pragma unroll
    for (int mt = 0; mt < 2; mt++) {
        #pragma unroll
        for (int sub = 0; sub < 2; sub++) {
            unsigned long long bk = 0ull;
            #pragma unroll
            for (int nt = 0; nt < 8; nt++) {
                #pragma unroll
                for (int j = 0; j < 2; j++) {
                    int cl = wCol + nt * 8 + 2 * (lid & 3) + j;
                    float f = acc[mt][nt][sub * 2 + j] * s_invb[cl];
                    unsigned long long k = make_key(__float_as_uint(f), mBase + cl);
                    if (k > bk) bk = k;
                }
            }
            unsigned long long o;
            o = __shfl_xor_sync(~0u, bk, 1); if (o > bk) bk = o;
            o = __shfl_xor_sync(~0u, bk, 2); if (o > bk) bk = o;
            if ((lid & 3) == 0) {
                int rowLocal = wRow + mt * 16 + sub * 8 + (lid >> 2);
                atomicMax(&s_best[rowLocal], bk);
            }
        }
    }
    __syncthreads();
    if (tid < TILE)
        atomicMax(&best[nBase + tid], s_best[tid]);
}

// ---------------- kernel 4: finalize (gather q_st + loss) ----------------
__global__ void finalize_kernel(float* __restrict__ q_out,
                                float* __restrict__ loss_out) {
    int n = blockIdx.x;
    int tid = threadIdx.x;   // 128 threads, one float4 each
    unsigned long long pk = g_best[n];
    unsigned idx = 0xFFFFFFFFu - (unsigned)(pk & 0xFFFFFFFFull);
    float dot = __uint_as_float(unflip_f((unsigned)(pk >> 32)));  // = x.cb_norm
    float4 v = *(const float4*)(g_cbn + (size_t)idx * KDIM + tid * 4);
    *(float4*)(q_out + (size_t)n * KDIM + tid * 4) = v;
    if (tid == 0 && loss_out)
        loss_out[n] = 1.0f - dot * g_invnx[n];
}

// ---------------- host launch ----------------
extern "C" void kernel_launch(void* const* d_in, const int* in_sizes, int n_in,
                              void* d_out, int out_size) {
    const float* x  = (const float*)d_in[0];
    const float* cb = (const float*)d_in[1];
    const int N = in_sizes[0] / KDIM;   // 32768
    const int M = in_sizes[1] / KDIM;   // 4096

    float* out = (float*)d_out;
    float* q_out = out;
    float* loss_out = nullptr;
    float* cb_out = nullptr;
    long long need_full = (long long)N * KDIM + N + (long long)M * KDIM;
    if ((long long)out_size >= need_full) {
        loss_out = out + (size_t)N * KDIM;
        cb_out = loss_out + N;
    } else if ((long long)out_size >= (long long)N * KDIM + N) {
        loss_out = out + (size_t)N * KDIM;
    }

    cudaFuncSetAttribute(vq_hmma_kernel,
                         cudaFuncAttributeMaxDynamicSharedMemorySize, DYN_SMEM);

    // device-symbol addresses MUST come from cudaGetSymbolAddress (R1 lesson)
    unsigned long long* bestp = nullptr;
    cudaGetSymbolAddress((void**)&bestp, g_best);

    norm_cb_kernel<<<M, 128>>>(cb, cb_out);
    norm_x_kernel<<<N, 128>>>(x);

    dim3 grid(M / TILE, N / TILE);   // codes inner -> B' (12 MB) hot in L2
    vq_hmma_kernel<<<grid, 256, DYN_SMEM>>>(bestp);

    finalize_kernel<<<N, 128>>>(q_out, loss_out);
}